// round 14
// baseline (speedup 1.0000x reference)
#include <cuda_runtime.h>
#include <cuda_bf16.h>
#include <math.h>
#include <stdint.h>

// ---------------- problem constants ----------------
#define NN 512
#define BB 32
#define SEQ 8
#define NTAB 7001
#define SZT (BB * NN * NN)

static __device__ __constant__ float SQLF = 0.22360679775f;   // sqrt(0.05)

// ---------------- device scratch (no runtime alloc allowed) ----------------
__device__ __nv_bfloat16 g_Ws[3][NN * NN];     // splits of W (constant, built once)
__device__ __nv_bfloat16 g_Cs[3][SZT];         // splits of Cov = diag(s) rho diag(s)
__device__ __nv_bfloat16 g_Ts[3][SZT];         // splits of T' = W*Cov
__device__ float g_diagP[16][BB * NN];         // deterministic diag partials (coltile*2+warpcol)
__device__ float g_uA[BB * NN], g_sA[BB * NN];
__device__ float g_uB[BB * NN], g_sB[BB * NN];
__device__ float g_ulin[BB * NN], g_diag[BB * NN];
__device__ float g_chi[BB * NN], g_sout[BB * NN];
__device__ float g_ue[BB * NN], g_se[BB * NN];
__device__ float g_ueraw[BB * NN], g_se2[BB * NN];

// Dawson-style tables
__device__ double d_I[NTAB], d_g[NTAB], d_h[NTAB];
__device__ float GTt[NTAB], GIt[NTAB], HIt[NTAB], XGf[NTAB];

// ---------------- helpers ----------------
__device__ __forceinline__ uint32_t smem_u32(const void* p) {
    uint32_t a;
    asm("{ .reg .u64 t; cvta.to.shared.u64 t, %1; cvt.u32.u64 %0, t; }" : "=r"(a) : "l"(p));
    return a;
}
__device__ __forceinline__ void split3(float v, __nv_bfloat16& b1, __nv_bfloat16& b2, __nv_bfloat16& b3) {
    b1 = __float2bfloat16_rn(v);
    float r = v - __bfloat162float(b1);
    b2 = __float2bfloat16_rn(r);
    float r2 = r - __bfloat162float(b2);
    b3 = __float2bfloat16_rn(r2);
}
__device__ __forceinline__ void mma16816_zc(float* d, const uint32_t* a, uint32_t b0, uint32_t b1) {
    asm volatile(
        "mma.sync.aligned.m16n8k16.row.col.f32.bf16.bf16.f32 "
        "{%0,%1,%2,%3}, {%4,%5,%6,%7}, {%8,%9}, {%10,%11,%12,%13};"
        : "=f"(d[0]), "=f"(d[1]), "=f"(d[2]), "=f"(d[3])
        : "r"(a[0]), "r"(a[1]), "r"(a[2]), "r"(a[3]), "r"(b0), "r"(b1),
          "f"(0.f), "f"(0.f), "f"(0.f), "f"(0.f));
}
__device__ __forceinline__ void mma16816(float* c, const uint32_t* a, uint32_t b0, uint32_t b1) {
    asm volatile(
        "mma.sync.aligned.m16n8k16.row.col.f32.bf16.bf16.f32 "
        "{%0,%1,%2,%3}, {%4,%5,%6,%7}, {%8,%9}, {%0,%1,%2,%3};"
        : "+f"(c[0]), "+f"(c[1]), "+f"(c[2]), "+f"(c[3])
        : "r"(a[0]), "r"(a[1]), "r"(a[2]), "r"(a[3]), "r"(b0), "r"(b1));
}
#define LDSM_X4(r0, r1, r2, r3, addr) \
    asm volatile("ldmatrix.sync.aligned.m8n8.x4.shared.b16 {%0,%1,%2,%3}, [%4];" \
                 : "=r"(r0), "=r"(r1), "=r"(r2), "=r"(r3) : "r"(addr))
#define CP_ASYNC16(dst, src) \
    asm volatile("cp.async.cg.shared.global [%0], [%1], 16;" :: "r"(dst), "l"(src))
#define CP_COMMIT() asm volatile("cp.async.commit_group;" ::: "memory")
#define CP_WAIT1()  asm volatile("cp.async.wait_group 1;" ::: "memory")
#define CP_WAIT0()  asm volatile("cp.async.wait_group 0;" ::: "memory")

// ---------------- table construction (fp64, matches numpy cumtrapz) ----------------
__device__ __forceinline__ double block_excl_scan(double local, double* part, int t) {
    part[t] = local;
    __syncthreads();
    for (int off = 1; off < 1024; off <<= 1) {
        double v = (t >= off) ? part[t - off] : 0.0;
        __syncthreads();
        part[t] += v;
        __syncthreads();
    }
    double incl = part[t];
    __syncthreads();
    return incl - local;
}

__global__ void build_tables_kernel() {
    const double DX = 14.0 / 7000.0;
    __shared__ double part[1024];
    int t = threadIdx.x;
    int start = t * 7;
    int end = start + 7;
    if (start > NTAB) start = NTAB;
    if (end > NTAB) end = NTAB;

    {
        double local = 0.0;
        for (int i = start; i < end; i++) {
            if (i > 0) {
                double x0 = -10.0 + (i - 1) * DX, x1 = -10.0 + i * DX;
                local += 0.5 * (exp(-x0 * x0) + exp(-x1 * x1)) * DX;
            }
        }
        double run = block_excl_scan(local, part, t);
        const double A0 = exp(-100.0) / 20.0;
        for (int i = start; i < end; i++) {
            if (i > 0) {
                double x0 = -10.0 + (i - 1) * DX, x1 = -10.0 + i * DX;
                run += 0.5 * (exp(-x0 * x0) + exp(-x1 * x1)) * DX;
            }
            d_I[i] = A0 + run;
            XGf[i] = (float)(-10.0 + i * DX);
        }
    }
    __syncthreads();
    for (int i = start; i < end; i++) {
        double x = -10.0 + i * DX;
        double g = exp(x * x) * d_I[i];
        d_g[i] = g;
        GTt[i] = (float)g;
    }
    __syncthreads();
    {
        double local = 0.0;
        for (int i = start; i < end; i++)
            if (i > 0) local += 0.5 * (d_g[i - 1] + d_g[i]) * DX;
        double run = block_excl_scan(local, part, t);
        for (int i = start; i < end; i++) {
            if (i > 0) run += 0.5 * (d_g[i - 1] + d_g[i]) * DX;
            GIt[i] = (float)run;
        }
    }
    __syncthreads();
    {
        double local = 0.0;
        for (int i = start; i < end; i++) {
            if (i > 0) {
                double xa = -10.0 + (i - 1) * DX, xb = -10.0 + i * DX;
                double fa = exp(-xa * xa) * d_g[i - 1] * d_g[i - 1];
                double fb = exp(-xb * xb) * d_g[i] * d_g[i];
                local += 0.5 * (fa + fb) * DX;
            }
        }
        double run = block_excl_scan(local, part, t);
        for (int i = start; i < end; i++) {
            if (i > 0) {
                double xa = -10.0 + (i - 1) * DX, xb = -10.0 + i * DX;
                double fa = exp(-xa * xa) * d_g[i - 1] * d_g[i - 1];
                double fb = exp(-xb * xb) * d_g[i] * d_g[i];
                run += 0.5 * (fa + fb) * DX;
            }
            double x = -10.0 + i * DX;
            d_h[i] = exp(x * x) * run;
        }
    }
    __syncthreads();
    {
        double local = 0.0;
        for (int i = start; i < end; i++)
            if (i > 0) local += 0.5 * (d_h[i - 1] + d_h[i]) * DX;
        double run = block_excl_scan(local, part, t);
        for (int i = start; i < end; i++) {
            if (i > 0) run += 0.5 * (d_h[i - 1] + d_h[i]) * DX;
            HIt[i] = (float)run;
        }
    }
}

// ---------------- small helper kernels ----------------
__global__ void init_copy_kernel(const float* __restrict__ u_in, const float* __restrict__ s_in) {
    int i = blockIdx.x * blockDim.x + threadIdx.x;
    if (i < BB * NN) { g_uA[i] = u_in[i]; g_sA[i] = s_in[i]; }
}

__global__ void ext_gemm_kernel(const float* __restrict__ We, const float* __restrict__ ue_in,
                                const float* __restrict__ se_in, const float* __restrict__ be) {
    int warp = threadIdx.x >> 5, lane = threadIdx.x & 31;
    int i = blockIdx.x * 8 + warp;
    int b = blockIdx.y;
    const float* wr = We + (size_t)i * NN;
    const float* ur = ue_in + (size_t)b * NN;
    const float* sr = se_in + (size_t)b * NN;
    float s1 = 0.f, s2 = 0.f;
    for (int k = lane; k < NN; k += 32) {
        float w = wr[k], sv = sr[k];
        s1 += w * ur[k];
        s2 += w * w * sv * sv;
    }
#pragma unroll
    for (int o = 16; o; o >>= 1) {
        s1 += __shfl_xor_sync(0xffffffffu, s1, o);
        s2 += __shfl_xor_sync(0xffffffffu, s2, o);
    }
    if (lane == 0) {
        g_ueraw[b * NN + i] = s1 + be[i];
        g_se2[b * NN + i] = s2;
    }
}

__global__ void ext_bn_kernel(const float* __restrict__ wme, const float* __restrict__ bme) {
    int i = blockIdx.x * blockDim.x + threadIdx.x;
    float m = 0.f;
    for (int b = 0; b < BB; b++) m += g_ueraw[b * NN + i];
    m *= (1.0f / BB);
    float v = 0.f;
    for (int b = 0; b < BB; b++) { float d = g_ueraw[b * NN + i] - m; v += d * d; }
    v *= (1.0f / BB);
    float f = wme[i] / sqrtf(v + 1e-5f);
    float af = fabsf(f);
    float bmv = bme[i];
    for (int b = 0; b < BB; b++) {
        int idx = b * NN + i;
        g_se[idx] = sqrtf(g_se2[idx]) * af;
        g_ue[idx] = (g_ueraw[idx] - m) * f + bmv;
    }
}

// per-step: u_lin = W u + b ; diag = fixed-order sum of 16 deterministic partials
__global__ void ulin_kernel(const float* __restrict__ W, const float* __restrict__ bias,
                            const float* __restrict__ u_cur) {
    int warp = threadIdx.x >> 5, lane = threadIdx.x & 31;
    int i = blockIdx.x * 8 + warp;
    int b = blockIdx.y;
    const float* wr = W + (size_t)i * NN;
    const float* ur = u_cur + (size_t)b * NN;
    float s1 = 0.f;
    for (int k = lane; k < NN; k += 32)
        s1 += wr[k] * ur[k];
    int idx = b * NN + i;
    float d = (lane < 16) ? g_diagP[lane][idx] : 0.f;
#pragma unroll
    for (int o = 16; o; o >>= 1) {
        s1 += __shfl_xor_sync(0xffffffffu, s1, o);
        d  += __shfl_xor_sync(0xffffffffu, d, o);
    }
    if (lane == 0) {
        g_ulin[idx] = s1 + bias[i];
        g_diag[idx] = d;
    }
}

__device__ __forceinline__ void interp_idx(float x, int& iq, float& fr) {
    float t = (x + 10.0f) * 500.0f;
    int i = (int)t;
    i = max(0, min(i, NTAB - 2));
    float x0 = __ldg(&XGf[i]);
    float x1 = __ldg(&XGf[i + 1]);
    if (x < x0 && i > 0) { i--; x1 = x0; x0 = __ldg(&XGf[i]); }
    else if (x >= x1 && i < NTAB - 2) { i++; x0 = x1; x1 = __ldg(&XGf[i + 1]); }
    iq = i;
    fr = (x - x0) / (x1 - x0);
}
__device__ __forceinline__ float interp_at(int i, float fr, const float* __restrict__ tab) {
    float lo = __ldg(&tab[i]);
    float hi = __ldg(&tab[i + 1]);
    return lo + fr * (hi - lo);
}

// BN + external + LIF activation: one WARP per neuron, lane = batch (BB == 32)
__global__ void bn_act_kernel(const float* __restrict__ wm, const float* __restrict__ bm,
                              float* __restrict__ u_nxt, float* __restrict__ s_nxt,
                              float* __restrict__ ou, float* __restrict__ os) {
    int warp = threadIdx.x >> 5, lane = threadIdx.x & 31;
    int i = blockIdx.x * 8 + warp;
    int idx = lane * NN + i;
    float ul = g_ulin[idx];
    float m = ul;
#pragma unroll
    for (int o = 16; o; o >>= 1) m += __shfl_xor_sync(0xffffffffu, m, o);
    m *= (1.0f / BB);
    float dd = ul - m;
    float v = dd * dd;
#pragma unroll
    for (int o = 16; o; o >>= 1) v += __shfl_xor_sync(0xffffffffu, v, o);
    v *= (1.0f / BB);
    float f = wm[i] / sqrtf(v + 1e-5f);
    float af = fabsf(f);
    float bmv = bm[i];

    float so = sqrtf(fmaxf(g_diag[idx], 0.f));
    float sbn = so * af;
    float se = g_se[idx];
    float st = sqrtf(sbn * sbn + se * se);
    float ut = (ul - m) * f + bmv + g_ue[idx];
    float ss = fmaxf(st, 1e-6f);
    float inv = 1.0f / (ss * SQLF);
    float ub = fminf(fmaxf((1.0f - ut) * inv, -10.f), 4.f);
    float lb = fminf(fmaxf((-ut) * inv, -10.f), 4.f);
    int iu, il; float fu, fl;
    interp_idx(ub, iu, fu);
    interp_idx(lb, il, fl);
    float dG = interp_at(iu, fu, GIt) - interp_at(il, fl, GIt);
    float ua = 1.0f / (5.0f + 40.0f * dG);
    float dH = fmaxf(interp_at(iu, fu, HIt) - interp_at(il, fl, HIt), 0.f);
    float sa = sqrtf(3200.0f * dH * ua * ua * ua);
    float dg = interp_at(iu, fu, GTt) - interp_at(il, fl, GTt);
    float chi = ua * ua * 40.0f * dg / (SQLF * fmaxf(sa, 1e-9f));
    u_nxt[idx] = ua;
    s_nxt[idx] = sa;
    g_chi[idx] = chi;
    g_sout[idx] = so;
    if (ou) { ou[idx] = ua; os[idx] = sa; }
}

// ---------------- split kernels ----------------
__global__ void wsplit_kernel(const float* __restrict__ W) {
    int q = blockIdx.x * blockDim.x + threadIdx.x;
    int base = q * 4;
    float4 v = *reinterpret_cast<const float4*>(&W[base]);
    float m[4] = {v.x, v.y, v.z, v.w};
    union { __nv_bfloat16 h[4]; uint2 u; } p1, p2, p3;
#pragma unroll
    for (int j = 0; j < 4; j++) split3(m[j], p1.h[j], p2.h[j], p3.h[j]);
    *reinterpret_cast<uint2*>(&g_Ws[0][base]) = p1.u;
    *reinterpret_cast<uint2*>(&g_Ws[1][base]) = p2.u;
    *reinterpret_cast<uint2*>(&g_Ws[2][base]) = p3.u;
}

__global__ void csplit0_kernel(const float* __restrict__ rho_in, const float* __restrict__ s_in) {
    int q = blockIdx.x * blockDim.x + threadIdx.x;
    int base = q * 4;
    int l = base & (NN - 1);
    int i = (base >> 9) & (NN - 1);
    int b = base >> 18;
    float si = s_in[b * NN + i];
    float4 sl = *reinterpret_cast<const float4*>(&s_in[b * NN + l]);
    float4 v = *reinterpret_cast<const float4*>(&rho_in[base]);
    float m[4] = {v.x * si * sl.x, v.y * si * sl.y, v.z * si * sl.z, v.w * si * sl.w};
    union { __nv_bfloat16 h[4]; uint2 u; } p1, p2, p3;
#pragma unroll
    for (int j = 0; j < 4; j++) split3(m[j], p1.h[j], p2.h[j], p3.h[j]);
    *reinterpret_cast<uint2*>(&g_Cs[0][base]) = p1.u;
    *reinterpret_cast<uint2*>(&g_Cs[1][base]) = p2.u;
    *reinterpret_cast<uint2*>(&g_Cs[2][base]) = p3.u;
}

// ---------------- HMMA batched GEMM: 256 thr, 8 warps (4x2), CTA tile 64x64, 3 CTAs/SM ----
// KC=32, 2-stage. Warp tile 16x32. SIX products: (0,0),(1,0),(0,1),(2,0),(1,1),(0,2).
// mode 0: T' = W @ Cov -> g_Ts splits + diag partials (grid 8x8xBB)
// mode 1: C = T' @ W^T symmetric -> rho epilogue + Cov_next splits; upper-tri 64x64 tiles
//         (36 per batch) with off-diagonal mirror via smem transpose (grid 36x1xBB)
#define KC2 32
#define ROW2 80                          // 32 bf16 = 64 B + 16 B pad
#define TILE64 (64 * ROW2)               // 5120 B
#define STAGE2 (6 * TILE64)              // 30720 B (A0..2 then B0..2)
#define SMEM_MMA (2 * STAGE2)            // 61440 B per CTA -> 3 CTAs/SM

__global__ void __launch_bounds__(256, 3)
mma_gemm_kernel(int mode, float* __restrict__ fdst, const float* __restrict__ s_nxt,
                const float* __restrict__ Wfull) {
    extern __shared__ char sm[];
    const uint32_t sb = smem_u32(sm);
    const int tid = threadIdx.x;
    const int wid = tid >> 5;
    const int lane = tid & 31;
    const int g = lane >> 2;
    const int tig = lane & 3;
    const int wr = wid & 3;             // warp row (16 rows of 64)
    const int wc = wid >> 2;            // warp col (32 cols of 64)
    const int b = blockIdx.z;

    int rowBase, colBase, coltile;
    bool offdiag = false;
    if (mode == 0) {
        coltile = blockIdx.x;           // 0..7 (64 cols each)
        rowBase = blockIdx.y * 64;
        colBase = coltile * 64;
    } else {
        int m = blockIdx.x;
        int t = 0, base = 0;
        while (base + t + 1 <= m) { t++; base += t; }
        int txm = t, tym = m - base;     // txm >= tym
        rowBase = tym * 64;
        colBase = txm * 64;
        offdiag = (txm != tym);
        coltile = 0;
    }

    const __nv_bfloat16* src[6];
    size_t abase, bbase;
    if (mode == 0) {
        src[0] = g_Ws[0]; src[1] = g_Ws[1]; src[2] = g_Ws[2];
        src[3] = g_Cs[0]; src[4] = g_Cs[1]; src[5] = g_Cs[2];
        abase = (size_t)rowBase * NN;                       // W: batchless
        bbase = ((size_t)(b * NN + colBase)) * NN;          // Cov symmetric
    } else {
        src[0] = g_Ts[0]; src[1] = g_Ts[1]; src[2] = g_Ts[2];
        src[3] = g_Ws[0]; src[4] = g_Ws[1]; src[5] = g_Ws[2];
        abase = ((size_t)(b * NN + rowBase)) * NN;
        bbase = (size_t)colBase * NN;                       // W^T: rows of W
    }

    auto issue_chunk = [&](int c, int st) {
        uint32_t dstBase = sb + st * STAGE2;
#pragma unroll
        for (int i = 0; i < 6; i++) {
            int idx = tid + i * 256;                         // 0..1535
            int tile = idx >> 8;                             // 0..5
            int rem = idx & 255;
            int r = rem >> 2, c4 = rem & 3;
            size_t go = (tile < 3 ? abase : bbase) + (size_t)r * NN + c * KC2 + c4 * 8;
            CP_ASYNC16(dstBase + tile * TILE64 + r * ROW2 + c4 * 16,
                       (const void*)(src[tile] + go));
        }
    };

    const uint32_t aBase = sb + (uint32_t)(wr * 16 + (lane & 15)) * ROW2 + ((lane >> 4) * 16);
    const uint32_t bBase = sb + 3 * TILE64
                              + (uint32_t)(wc * 32 + ((lane >> 4) << 3) + (lane & 7)) * ROW2
                              + (((lane >> 3) & 1) * 16);

    float racc[4][4];
#pragma unroll
    for (int j = 0; j < 4; j++)
#pragma unroll
        for (int q = 0; q < 4; q++) racc[j][q] = 0.f;

    issue_chunk(0, 0);
    CP_COMMIT();

    for (int c = 0; c < 16; c++) {
        int st = c & 1;
        if (c + 1 < 16) {
            issue_chunk(c + 1, (c + 1) & 1);
            CP_COMMIT();
            CP_WAIT1();
        } else {
            CP_WAIT0();
        }
        __syncthreads();

        uint32_t stOff = (uint32_t)st * STAGE2;
#pragma unroll
        for (int ks = 0; ks < 2; ks++) {
            uint32_t kOff = stOff + ks * 32;
            uint32_t af[3][4];
#pragma unroll
            for (int p = 0; p < 3; p++)
                LDSM_X4(af[p][0], af[p][1], af[p][2], af[p][3],
                        aBase + kOff + p * TILE64);
            uint32_t bfr[3][4][2];
#pragma unroll
            for (int q = 0; q < 3; q++) {
#pragma unroll
                for (int j = 0; j < 2; j++)
                    LDSM_X4(bfr[q][2 * j][0], bfr[q][2 * j][1], bfr[q][2 * j + 1][0], bfr[q][2 * j + 1][1],
                            bBase + kOff + q * TILE64 + j * (16 * ROW2));
            }
#pragma unroll
            for (int n4 = 0; n4 < 4; n4++) {
                float ta[4];
                mma16816_zc(ta, af[0], bfr[0][n4][0], bfr[0][n4][1]);   // (0,0) lead
                racc[n4][0] += ta[0]; racc[n4][1] += ta[1];
                racc[n4][2] += ta[2]; racc[n4][3] += ta[3];
                float c1[4], c2[4];
                mma16816_zc(c1, af[1], bfr[0][n4][0], bfr[0][n4][1]);   // (1,0)
                mma16816_zc(c2, af[0], bfr[1][n4][0], bfr[1][n4][1]);   // (0,1)
                mma16816(c1, af[2], bfr[0][n4][0], bfr[0][n4][1]);      // (2,0)
                mma16816(c2, af[1], bfr[1][n4][0], bfr[1][n4][1]);      // (1,1)
                mma16816(c2, af[0], bfr[2][n4][0], bfr[2][n4][1]);      // (0,2)
                racc[n4][0] += c1[0]; racc[n4][1] += c1[1];
                racc[n4][2] += c1[2]; racc[n4][3] += c1[3];
                racc[n4][0] += c2[0]; racc[n4][1] += c2[1];
                racc[n4][2] += c2[2]; racc[n4][3] += c2[3];
            }
        }
        __syncthreads();
    }

    // ---- epilogue (warp tile 16x32: rows wr*16.., cols wc*32..) ----
    if (mode == 0) {
#pragma unroll
        for (int half = 0; half < 2; half++) {
            int gi = rowBase + wr * 16 + g + half * 8;
            size_t rowo = ((size_t)(b * NN + gi)) * NN;
            float part = 0.f;
#pragma unroll
            for (int n4 = 0; n4 < 4; n4++) {
                int l0 = colBase + wc * 32 + n4 * 8 + tig * 2;
                float c0 = racc[n4][half * 2 + 0];
                float c1 = racc[n4][half * 2 + 1];
                float2 wv = *reinterpret_cast<const float2*>(&Wfull[(size_t)gi * NN + l0]);
                part += c0 * wv.x + c1 * wv.y;
                __nv_bfloat16 x1, x2, x3, y1, y2, y3;
                split3(c0, x1, x2, x3);
                split3(c1, y1, y2, y3);
                union { __nv_bfloat16 h[2]; uint32_t u; } u1, u2, u3;
                u1.h[0] = x1; u1.h[1] = y1;
                u2.h[0] = x2; u2.h[1] = y2;
                u3.h[0] = x3; u3.h[1] = y3;
                *reinterpret_cast<uint32_t*>(&g_Ts[0][rowo + l0]) = u1.u;
                *reinterpret_cast<uint32_t*>(&g_Ts[1][rowo + l0]) = u2.u;
                *reinterpret_cast<uint32_t*>(&g_Ts[2][rowo + l0]) = u3.u;
            }
            part += __shfl_xor_sync(0xffffffffu, part, 1);
            part += __shfl_xor_sync(0xffffffffu, part, 2);
            if (tig == 0)
                g_diagP[coltile * 2 + wc][b * NN + gi] = part;
        }
    } else {
        float* tb = (float*)sm;                 // 64 x 68 f32 transpose buffer (17.4 KB)
#pragma unroll
        for (int half = 0; half < 2; half++) {
            int gl = wr * 16 + g + half * 8;     // local row 0..63
            int gi = rowBase + gl;
            size_t rowo = ((size_t)(b * NN + gi)) * NN;
            float chI = __ldg(&g_chi[b * NN + gi]);
            float soI = __ldg(&g_sout[b * NN + gi]);
            float snI = __ldg(&s_nxt[b * NN + gi]);
#pragma unroll
            for (int n4 = 0; n4 < 4; n4++) {
                int lc = wc * 32 + n4 * 8 + tig * 2;   // local col 0..63
                int l0 = colBase + lc;
                float rv[2], cvv[2];
#pragma unroll
                for (int q = 0; q < 2; q++) {
                    int l = l0 + q;
                    float cv = racc[n4][half * 2 + q];
                    float chL = __ldg(&g_chi[b * NN + l]);
                    float soL = __ldg(&g_sout[b * NN + l]);
                    float snL = __ldg(&s_nxt[b * NN + l]);
                    float denom = soI * soL;
                    float qq = (denom > 1e-12f) ? cv / denom : 0.0f;
                    rv[q] = (gi == l) ? 1.0f : chI * chL * qq;
                    cvv[q] = rv[q] * snI * snL;
                    if (offdiag) tb[(lc + q) * 68 + gl] = rv[q];
                }
                __nv_bfloat16 x1, x2, x3, y1, y2, y3;
                split3(cvv[0], x1, x2, x3);
                split3(cvv[1], y1, y2, y3);
                union { __nv_bfloat16 h[2]; uint32_t u; } u1, u2, u3;
                u1.h[0] = x1; u1.h[1] = y1;
                u2.h[0] = x2; u2.h[1] = y2;
                u3.h[0] = x3; u3.h[1] = y3;
                *reinterpret_cast<uint32_t*>(&g_Cs[0][rowo + l0]) = u1.u;
                *reinterpret_cast<uint32_t*>(&g_Cs[1][rowo + l0]) = u2.u;
                *reinterpret_cast<uint32_t*>(&g_Cs[2][rowo + l0]) = u3.u;
                if (fdst)
                    *reinterpret_cast<float2*>(&fdst[rowo + l0]) = make_float2(rv[0], rv[1]);
            }
        }
        if (offdiag) {
            __syncthreads();
            // mirror: global rows colBase..+64, cols rowBase..+64
            int r2 = tid >> 2;                  // 0..63
            int c0 = (tid & 3) * 16;
            int giM = colBase + r2;
            size_t mrow = ((size_t)(b * NN + giM)) * NN + rowBase + c0;
            const float* trow = tb + r2 * 68 + c0;
            float* frow = fdst ? (fdst + mrow) : (float*)0;
            float snI = __ldg(&s_nxt[b * NN + giM]);
#pragma unroll
            for (int j = 0; j < 16; j += 4) {
                float r0 = trow[j + 0], r1 = trow[j + 1], r2v = trow[j + 2], r3 = trow[j + 3];
                float4 snL = *reinterpret_cast<const float4*>(&s_nxt[b * NN + rowBase + c0 + j]);
                float v0 = r0 * snI * snL.x, v1 = r1 * snI * snL.y;
                float v2 = r2v * snI * snL.z, v3 = r3 * snI * snL.w;
                union { __nv_bfloat16 h[4]; uint2 u; } p1, p2, p3;
                split3(v0, p1.h[0], p2.h[0], p3.h[0]);
                split3(v1, p1.h[1], p2.h[1], p3.h[1]);
                split3(v2, p1.h[2], p2.h[2], p3.h[2]);
                split3(v3, p1.h[3], p2.h[3], p3.h[3]);
                *reinterpret_cast<uint2*>(&g_Cs[0][mrow + j]) = p1.u;
                *reinterpret_cast<uint2*>(&g_Cs[1][mrow + j]) = p2.u;
                *reinterpret_cast<uint2*>(&g_Cs[2][mrow + j]) = p3.u;
                if (frow)
                    *reinterpret_cast<float4*>(frow + j) = make_float4(r0, r1, r2v, r3);
            }
        }
    }
}

// ---------------- launch ----------------
extern "C" void kernel_launch(void* const* d_in, const int* in_sizes, int n_in,
                              void* d_out, int out_size) {
    const float* u_in     = (const float*)d_in[0];
    const float* s_in     = (const float*)d_in[1];
    const float* rho_in   = (const float*)d_in[2];
    const float* uext     = (const float*)d_in[3];
    const float* sext     = (const float*)d_in[4];
    const float* W        = (const float*)d_in[5];
    const float* bias     = (const float*)d_in[6];
    const float* Wext     = (const float*)d_in[7];
    const float* bext     = (const float*)d_in[8];
    const float* wmean    = (const float*)d_in[9];
    const float* bmean    = (const float*)d_in[10];
    const float* wmeanext = (const float*)d_in[11];
    const float* bmeanext = (const float*)d_in[12];
    (void)in_sizes; (void)n_in; (void)out_size;

    float* out = (float*)d_out;
    float* out_u = out;
    float* out_s = out + BB * NN;
    float* out_rho = out + 2 * BB * NN;

    cudaFuncSetAttribute(mma_gemm_kernel, cudaFuncAttributeMaxDynamicSharedMemorySize, SMEM_MMA);

    float *uA, *sA, *uB, *sB;
    cudaGetSymbolAddress((void**)&uA, g_uA);
    cudaGetSymbolAddress((void**)&sA, g_sA);
    cudaGetSymbolAddress((void**)&uB, g_uB);
    cudaGetSymbolAddress((void**)&sB, g_sB);

    dim3 g0(8, 8, BB);       // GEMM1: 64x64 tiles, full grid
    dim3 g1(36, 1, BB);      // GEMM2: upper-triangle 64x64 tiles
    float* u_cur = uA; float* s_cur = sA;
    float* u_nxt = uB; float* s_nxt = sB;

    // t = 0 (ordered so mma_gemm mode 0 is launch index 3 -> ncu profiles it)
    init_copy_kernel<<<32, 512>>>(u_in, s_in);                               // 0
    wsplit_kernel<<<NN * NN / 4 / 256, 256>>>(W);                            // 1
    csplit0_kernel<<<SZT / 4 / 256, 256>>>(rho_in, s_in);                    // 2
    mma_gemm_kernel<<<g0, 256, SMEM_MMA>>>(0, (float*)nullptr, s_cur, W);    // 3  <-- profiled
    build_tables_kernel<<<1, 1024>>>();                                      // 4
    ext_gemm_kernel<<<dim3(64, 32), 256>>>(Wext, uext, sext, bext);          // 5
    ext_bn_kernel<<<4, 128>>>(wmeanext, bmeanext);                           // 6
    ulin_kernel<<<dim3(64, 32), 256>>>(W, bias, u_cur);                      // 7
    bn_act_kernel<<<64, 256>>>(wmean, bmean, u_nxt, s_nxt,
                               (float*)nullptr, (float*)nullptr);            // 8
    mma_gemm_kernel<<<g1, 256, SMEM_MMA>>>(1, (float*)nullptr, s_nxt, W);    // 9
    { float* t = u_cur; u_cur = u_nxt; u_nxt = t; }
    { float* t = s_cur; s_cur = s_nxt; s_nxt = t; }

    for (int t = 1; t < SEQ; t++) {
        bool last = (t == SEQ - 1);
        mma_gemm_kernel<<<g0, 256, SMEM_MMA>>>(0, (float*)nullptr, s_cur, W);
        ulin_kernel<<<dim3(64, 32), 256>>>(W, bias, u_cur);
        bn_act_kernel<<<64, 256>>>(wmean, bmean, u_nxt, s_nxt,
                                   last ? out_u : (float*)nullptr,
                                   last ? out_s : (float*)nullptr);
        mma_gemm_kernel<<<g1, 256, SMEM_MMA>>>(1, last ? out_rho : (float*)nullptr, s_nxt, W);
        float* tu = u_cur; u_cur = u_nxt; u_nxt = tu;
        float* ts = s_cur; s_cur = s_nxt; s_nxt = ts;
    }
}

// round 15
// speedup vs baseline: 1.0636x; 1.0636x over previous
#include <cuda_runtime.h>
#include <cuda_bf16.h>
#include <math.h>
#include <stdint.h>

// ---------------- problem constants ----------------
#define NN 512
#define BB 32
#define SEQ 8
#define NTAB 7001
#define SZT (BB * NN * NN)

static __device__ __constant__ float SQLF = 0.22360679775f;   // sqrt(0.05)

// ---------------- device scratch (no runtime alloc allowed) ----------------
__device__ __nv_bfloat16 g_Ws[3][NN * NN];     // splits of W (constant, built once)
__device__ __nv_bfloat16 g_Cs[3][SZT];         // splits of Cov = diag(s) rho diag(s)
__device__ __nv_bfloat16 g_Ts[3][SZT];         // splits of T' = W*Cov
__device__ float g_diagP[16][BB * NN];         // deterministic diag partials (coltile*2+warpcol)
__device__ float g_uA[BB * NN], g_sA[BB * NN];
__device__ float g_uB[BB * NN], g_sB[BB * NN];
__device__ float g_ulin[BB * NN], g_diag[BB * NN];
__device__ float g_chi[BB * NN], g_sout[BB * NN];
__device__ float g_ue[BB * NN], g_se[BB * NN];
__device__ float g_ueraw[BB * NN], g_se2[BB * NN];

// Dawson-style tables
__device__ double d_I[NTAB], d_g[NTAB], d_h[NTAB];
__device__ float GTt[NTAB], GIt[NTAB], HIt[NTAB], XGf[NTAB];

// ---------------- helpers ----------------
__device__ __forceinline__ uint32_t smem_u32(const void* p) {
    uint32_t a;
    asm("{ .reg .u64 t; cvta.to.shared.u64 t, %1; cvt.u32.u64 %0, t; }" : "=r"(a) : "l"(p));
    return a;
}
__device__ __forceinline__ void split3(float v, __nv_bfloat16& b1, __nv_bfloat16& b2, __nv_bfloat16& b3) {
    b1 = __float2bfloat16_rn(v);
    float r = v - __bfloat162float(b1);
    b2 = __float2bfloat16_rn(r);
    float r2 = r - __bfloat162float(b2);
    b3 = __float2bfloat16_rn(r2);
}
__device__ __forceinline__ void mma16816_zc(float* d, const uint32_t* a, uint32_t b0, uint32_t b1) {
    asm volatile(
        "mma.sync.aligned.m16n8k16.row.col.f32.bf16.bf16.f32 "
        "{%0,%1,%2,%3}, {%4,%5,%6,%7}, {%8,%9}, {%10,%11,%12,%13};"
        : "=f"(d[0]), "=f"(d[1]), "=f"(d[2]), "=f"(d[3])
        : "r"(a[0]), "r"(a[1]), "r"(a[2]), "r"(a[3]), "r"(b0), "r"(b1),
          "f"(0.f), "f"(0.f), "f"(0.f), "f"(0.f));
}
__device__ __forceinline__ void mma16816(float* c, const uint32_t* a, uint32_t b0, uint32_t b1) {
    asm volatile(
        "mma.sync.aligned.m16n8k16.row.col.f32.bf16.bf16.f32 "
        "{%0,%1,%2,%3}, {%4,%5,%6,%7}, {%8,%9}, {%0,%1,%2,%3};"
        : "+f"(c[0]), "+f"(c[1]), "+f"(c[2]), "+f"(c[3])
        : "r"(a[0]), "r"(a[1]), "r"(a[2]), "r"(a[3]), "r"(b0), "r"(b1));
}
#define LDSM_X4(r0, r1, r2, r3, addr) \
    asm volatile("ldmatrix.sync.aligned.m8n8.x4.shared.b16 {%0,%1,%2,%3}, [%4];" \
                 : "=r"(r0), "=r"(r1), "=r"(r2), "=r"(r3) : "r"(addr))
#define CP_ASYNC16(dst, src) \
    asm volatile("cp.async.cg.shared.global [%0], [%1], 16;" :: "r"(dst), "l"(src))
#define CP_COMMIT() asm volatile("cp.async.commit_group;" ::: "memory")
#define CP_WAIT1()  asm volatile("cp.async.wait_group 1;" ::: "memory")
#define CP_WAIT0()  asm volatile("cp.async.wait_group 0;" ::: "memory")

// ---------------- table construction (fp64, matches numpy cumtrapz) ----------------
__device__ __forceinline__ double block_excl_scan(double local, double* part, int t) {
    part[t] = local;
    __syncthreads();
    for (int off = 1; off < 1024; off <<= 1) {
        double v = (t >= off) ? part[t - off] : 0.0;
        __syncthreads();
        part[t] += v;
        __syncthreads();
    }
    double incl = part[t];
    __syncthreads();
    return incl - local;
}

__global__ void build_tables_kernel() {
    const double DX = 14.0 / 7000.0;
    __shared__ double part[1024];
    int t = threadIdx.x;
    int start = t * 7;
    int end = start + 7;
    if (start > NTAB) start = NTAB;
    if (end > NTAB) end = NTAB;

    {
        double local = 0.0;
        for (int i = start; i < end; i++) {
            if (i > 0) {
                double x0 = -10.0 + (i - 1) * DX, x1 = -10.0 + i * DX;
                local += 0.5 * (exp(-x0 * x0) + exp(-x1 * x1)) * DX;
            }
        }
        double run = block_excl_scan(local, part, t);
        const double A0 = exp(-100.0) / 20.0;
        for (int i = start; i < end; i++) {
            if (i > 0) {
                double x0 = -10.0 + (i - 1) * DX, x1 = -10.0 + i * DX;
                run += 0.5 * (exp(-x0 * x0) + exp(-x1 * x1)) * DX;
            }
            d_I[i] = A0 + run;
            XGf[i] = (float)(-10.0 + i * DX);
        }
    }
    __syncthreads();
    for (int i = start; i < end; i++) {
        double x = -10.0 + i * DX;
        double g = exp(x * x) * d_I[i];
        d_g[i] = g;
        GTt[i] = (float)g;
    }
    __syncthreads();
    {
        double local = 0.0;
        for (int i = start; i < end; i++)
            if (i > 0) local += 0.5 * (d_g[i - 1] + d_g[i]) * DX;
        double run = block_excl_scan(local, part, t);
        for (int i = start; i < end; i++) {
            if (i > 0) run += 0.5 * (d_g[i - 1] + d_g[i]) * DX;
            GIt[i] = (float)run;
        }
    }
    __syncthreads();
    {
        double local = 0.0;
        for (int i = start; i < end; i++) {
            if (i > 0) {
                double xa = -10.0 + (i - 1) * DX, xb = -10.0 + i * DX;
                double fa = exp(-xa * xa) * d_g[i - 1] * d_g[i - 1];
                double fb = exp(-xb * xb) * d_g[i] * d_g[i];
                local += 0.5 * (fa + fb) * DX;
            }
        }
        double run = block_excl_scan(local, part, t);
        for (int i = start; i < end; i++) {
            if (i > 0) {
                double xa = -10.0 + (i - 1) * DX, xb = -10.0 + i * DX;
                double fa = exp(-xa * xa) * d_g[i - 1] * d_g[i - 1];
                double fb = exp(-xb * xb) * d_g[i] * d_g[i];
                run += 0.5 * (fa + fb) * DX;
            }
            double x = -10.0 + i * DX;
            d_h[i] = exp(x * x) * run;
        }
    }
    __syncthreads();
    {
        double local = 0.0;
        for (int i = start; i < end; i++)
            if (i > 0) local += 0.5 * (d_h[i - 1] + d_h[i]) * DX;
        double run = block_excl_scan(local, part, t);
        for (int i = start; i < end; i++) {
            if (i > 0) run += 0.5 * (d_h[i - 1] + d_h[i]) * DX;
            HIt[i] = (float)run;
        }
    }
}

// ---------------- small helper kernels ----------------
__global__ void init_copy_kernel(const float* __restrict__ u_in, const float* __restrict__ s_in) {
    int i = blockIdx.x * blockDim.x + threadIdx.x;
    if (i < BB * NN) { g_uA[i] = u_in[i]; g_sA[i] = s_in[i]; }
}

__global__ void ext_gemm_kernel(const float* __restrict__ We, const float* __restrict__ ue_in,
                                const float* __restrict__ se_in, const float* __restrict__ be) {
    int warp = threadIdx.x >> 5, lane = threadIdx.x & 31;
    int i = blockIdx.x * 8 + warp;
    int b = blockIdx.y;
    const float* wr = We + (size_t)i * NN;
    const float* ur = ue_in + (size_t)b * NN;
    const float* sr = se_in + (size_t)b * NN;
    float s1 = 0.f, s2 = 0.f;
    for (int k = lane; k < NN; k += 32) {
        float w = wr[k], sv = sr[k];
        s1 += w * ur[k];
        s2 += w * w * sv * sv;
    }
#pragma unroll
    for (int o = 16; o; o >>= 1) {
        s1 += __shfl_xor_sync(0xffffffffu, s1, o);
        s2 += __shfl_xor_sync(0xffffffffu, s2, o);
    }
    if (lane == 0) {
        g_ueraw[b * NN + i] = s1 + be[i];
        g_se2[b * NN + i] = s2;
    }
}

__global__ void ext_bn_kernel(const float* __restrict__ wme, const float* __restrict__ bme) {
    int i = blockIdx.x * blockDim.x + threadIdx.x;
    float m = 0.f;
    for (int b = 0; b < BB; b++) m += g_ueraw[b * NN + i];
    m *= (1.0f / BB);
    float v = 0.f;
    for (int b = 0; b < BB; b++) { float d = g_ueraw[b * NN + i] - m; v += d * d; }
    v *= (1.0f / BB);
    float f = wme[i] / sqrtf(v + 1e-5f);
    float af = fabsf(f);
    float bmv = bme[i];
    for (int b = 0; b < BB; b++) {
        int idx = b * NN + i;
        g_se[idx] = sqrtf(g_se2[idx]) * af;
        g_ue[idx] = (g_ueraw[idx] - m) * f + bmv;
    }
}

// per-step: u_lin = W u + b ; diag = fixed-order sum of 16 deterministic partials
__global__ void ulin_kernel(const float* __restrict__ W, const float* __restrict__ bias,
                            const float* __restrict__ u_cur) {
    int warp = threadIdx.x >> 5, lane = threadIdx.x & 31;
    int i = blockIdx.x * 8 + warp;
    int b = blockIdx.y;
    const float* wr = W + (size_t)i * NN;
    const float* ur = u_cur + (size_t)b * NN;
    float s1 = 0.f;
    for (int k = lane; k < NN; k += 32)
        s1 += wr[k] * ur[k];
    int idx = b * NN + i;
    float d = (lane < 16) ? g_diagP[lane][idx] : 0.f;
#pragma unroll
    for (int o = 16; o; o >>= 1) {
        s1 += __shfl_xor_sync(0xffffffffu, s1, o);
        d  += __shfl_xor_sync(0xffffffffu, d, o);
    }
    if (lane == 0) {
        g_ulin[idx] = s1 + bias[i];
        g_diag[idx] = d;
    }
}

__device__ __forceinline__ void interp_idx(float x, int& iq, float& fr) {
    float t = (x + 10.0f) * 500.0f;
    int i = (int)t;
    i = max(0, min(i, NTAB - 2));
    float x0 = __ldg(&XGf[i]);
    float x1 = __ldg(&XGf[i + 1]);
    if (x < x0 && i > 0) { i--; x1 = x0; x0 = __ldg(&XGf[i]); }
    else if (x >= x1 && i < NTAB - 2) { i++; x0 = x1; x1 = __ldg(&XGf[i + 1]); }
    iq = i;
    fr = (x - x0) / (x1 - x0);
}
__device__ __forceinline__ float interp_at(int i, float fr, const float* __restrict__ tab) {
    float lo = __ldg(&tab[i]);
    float hi = __ldg(&tab[i + 1]);
    return lo + fr * (hi - lo);
}

// BN + external + LIF activation: one WARP per neuron, lane = batch (BB == 32)
__global__ void bn_act_kernel(const float* __restrict__ wm, const float* __restrict__ bm,
                              float* __restrict__ u_nxt, float* __restrict__ s_nxt,
                              float* __restrict__ ou, float* __restrict__ os) {
    int warp = threadIdx.x >> 5, lane = threadIdx.x & 31;
    int i = blockIdx.x * 8 + warp;
    int idx = lane * NN + i;
    float ul = g_ulin[idx];
    float m = ul;
#pragma unroll
    for (int o = 16; o; o >>= 1) m += __shfl_xor_sync(0xffffffffu, m, o);
    m *= (1.0f / BB);
    float dd = ul - m;
    float v = dd * dd;
#pragma unroll
    for (int o = 16; o; o >>= 1) v += __shfl_xor_sync(0xffffffffu, v, o);
    v *= (1.0f / BB);
    float f = wm[i] / sqrtf(v + 1e-5f);
    float af = fabsf(f);
    float bmv = bm[i];

    float so = sqrtf(fmaxf(g_diag[idx], 0.f));
    float sbn = so * af;
    float se = g_se[idx];
    float st = sqrtf(sbn * sbn + se * se);
    float ut = (ul - m) * f + bmv + g_ue[idx];
    float ss = fmaxf(st, 1e-6f);
    float inv = 1.0f / (ss * SQLF);
    float ub = fminf(fmaxf((1.0f - ut) * inv, -10.f), 4.f);
    float lb = fminf(fmaxf((-ut) * inv, -10.f), 4.f);
    int iu, il; float fu, fl;
    interp_idx(ub, iu, fu);
    interp_idx(lb, il, fl);
    float dG = interp_at(iu, fu, GIt) - interp_at(il, fl, GIt);
    float ua = 1.0f / (5.0f + 40.0f * dG);
    float dH = fmaxf(interp_at(iu, fu, HIt) - interp_at(il, fl, HIt), 0.f);
    float sa = sqrtf(3200.0f * dH * ua * ua * ua);
    float dg = interp_at(iu, fu, GTt) - interp_at(il, fl, GTt);
    float chi = ua * ua * 40.0f * dg / (SQLF * fmaxf(sa, 1e-9f));
    u_nxt[idx] = ua;
    s_nxt[idx] = sa;
    g_chi[idx] = chi;
    g_sout[idx] = so;
    if (ou) { ou[idx] = ua; os[idx] = sa; }
}

// ---------------- split kernels ----------------
__global__ void wsplit_kernel(const float* __restrict__ W) {
    int q = blockIdx.x * blockDim.x + threadIdx.x;
    int base = q * 4;
    float4 v = *reinterpret_cast<const float4*>(&W[base]);
    float m[4] = {v.x, v.y, v.z, v.w};
    union { __nv_bfloat16 h[4]; uint2 u; } p1, p2, p3;
#pragma unroll
    for (int j = 0; j < 4; j++) split3(m[j], p1.h[j], p2.h[j], p3.h[j]);
    *reinterpret_cast<uint2*>(&g_Ws[0][base]) = p1.u;
    *reinterpret_cast<uint2*>(&g_Ws[1][base]) = p2.u;
    *reinterpret_cast<uint2*>(&g_Ws[2][base]) = p3.u;
}

__global__ void csplit0_kernel(const float* __restrict__ rho_in, const float* __restrict__ s_in) {
    int q = blockIdx.x * blockDim.x + threadIdx.x;
    int base = q * 4;
    int l = base & (NN - 1);
    int i = (base >> 9) & (NN - 1);
    int b = base >> 18;
    float si = s_in[b * NN + i];
    float4 sl = *reinterpret_cast<const float4*>(&s_in[b * NN + l]);
    float4 v = *reinterpret_cast<const float4*>(&rho_in[base]);
    float m[4] = {v.x * si * sl.x, v.y * si * sl.y, v.z * si * sl.z, v.w * si * sl.w};
    union { __nv_bfloat16 h[4]; uint2 u; } p1, p2, p3;
#pragma unroll
    for (int j = 0; j < 4; j++) split3(m[j], p1.h[j], p2.h[j], p3.h[j]);
    *reinterpret_cast<uint2*>(&g_Cs[0][base]) = p1.u;
    *reinterpret_cast<uint2*>(&g_Cs[1][base]) = p2.u;
    *reinterpret_cast<uint2*>(&g_Cs[2][base]) = p3.u;
}

// ============ GEMM1: 256 thr, 8 warps (4x2), CTA tile 128x64, 2 CTAs/SM (round-13 winner) ====
// T' = W @ Cov -> g_Ts splits + diag partials (grid 8x4xBB)
#define KC2 32
#define ROW2 80                          // 32 bf16 = 64 B + 16 B pad
#define TILEA2 (128 * ROW2)              // 10240 B
#define TILEB2 (64 * ROW2)               // 5120 B
#define BOFF2 (3 * TILEA2)               // 30720
#define STAGE2 (3 * TILEA2 + 3 * TILEB2) // 46080 B
#define SMEM_G1 (2 * STAGE2)             // 92160 B per CTA -> 2 CTAs/SM

__global__ void __launch_bounds__(256, 2)
mma_gemm1_kernel(const float* __restrict__ Wfull) {
    extern __shared__ char sm[];
    const uint32_t sb = smem_u32(sm);
    const int tid = threadIdx.x;
    const int wid = tid >> 5;
    const int lane = tid & 31;
    const int g = lane >> 2;
    const int tig = lane & 3;
    const int wr = wid & 3;             // warp row (32 rows of 128)
    const int wc = wid >> 2;            // warp col (32 cols of 64)
    const int b = blockIdx.z;
    const int coltile = blockIdx.x;     // 0..7
    const int rowBase = blockIdx.y * 128;
    const int colBase = coltile * 64;

    const __nv_bfloat16* src[6] = {g_Ws[0], g_Ws[1], g_Ws[2], g_Cs[0], g_Cs[1], g_Cs[2]};
    const size_t abase = (size_t)rowBase * NN;              // W: batchless
    const size_t bbase = ((size_t)(b * NN + colBase)) * NN; // Cov symmetric

    auto issue_chunk = [&](int c, int st) {
        uint32_t dstBase = sb + st * STAGE2;
#pragma unroll
        for (int i = 0; i < 9; i++) {
            int idx = tid + i * 256;
            if (idx < 1536) {
                int tile = idx >> 9;
                int rem = idx & 511;
                int r = rem >> 2, c4 = rem & 3;
                size_t go = abase + (size_t)r * NN + c * KC2 + c4 * 8;
                CP_ASYNC16(dstBase + tile * TILEA2 + r * ROW2 + c4 * 16,
                           (const void*)(src[tile] + go));
            } else {
                int j = idx - 1536;
                int q = j >> 8;
                int rem = j & 255;
                int r = rem >> 2, c4 = rem & 3;
                size_t go = bbase + (size_t)r * NN + c * KC2 + c4 * 8;
                CP_ASYNC16(dstBase + BOFF2 + q * TILEB2 + r * ROW2 + c4 * 16,
                           (const void*)(src[3 + q] + go));
            }
        }
    };

    const uint32_t aBase = sb + (uint32_t)(wr * 32 + (lane & 15)) * ROW2 + ((lane >> 4) * 16);
    const uint32_t bBase = sb + BOFF2 + (uint32_t)(wc * 32 + ((lane >> 4) << 3) + (lane & 7)) * ROW2
                              + (((lane >> 3) & 1) * 16);

    float racc[2][4][4];
#pragma unroll
    for (int i = 0; i < 2; i++)
#pragma unroll
        for (int j = 0; j < 4; j++)
#pragma unroll
            for (int q = 0; q < 4; q++) racc[i][j][q] = 0.f;

    issue_chunk(0, 0);
    CP_COMMIT();

    for (int c = 0; c < 16; c++) {
        int st = c & 1;
        if (c + 1 < 16) {
            issue_chunk(c + 1, (c + 1) & 1);
            CP_COMMIT();
            CP_WAIT1();
        } else {
            CP_WAIT0();
        }
        __syncthreads();

        uint32_t stOff = (uint32_t)st * STAGE2;
#pragma unroll
        for (int ks = 0; ks < 2; ks++) {
            uint32_t kOff = stOff + ks * 32;
            uint32_t af[3][2][4];
#pragma unroll
            for (int p = 0; p < 3; p++) {
#pragma unroll
                for (int ms = 0; ms < 2; ms++)
                    LDSM_X4(af[p][ms][0], af[p][ms][1], af[p][ms][2], af[p][ms][3],
                            aBase + kOff + p * TILEA2 + ms * (16 * ROW2));
            }
            uint32_t bfr[3][4][2];
#pragma unroll
            for (int q = 0; q < 3; q++) {
#pragma unroll
                for (int j = 0; j < 2; j++)
                    LDSM_X4(bfr[q][2 * j][0], bfr[q][2 * j][1], bfr[q][2 * j + 1][0], bfr[q][2 * j + 1][1],
                            bBase + kOff + q * TILEB2 + j * (16 * ROW2));
            }
#pragma unroll
            for (int ms = 0; ms < 2; ms++) {
#pragma unroll
                for (int n4 = 0; n4 < 4; n4++) {
                    float ta[4];
                    mma16816_zc(ta, af[0][ms], bfr[0][n4][0], bfr[0][n4][1]);   // (0,0) lead
                    racc[ms][n4][0] += ta[0]; racc[ms][n4][1] += ta[1];
                    racc[ms][n4][2] += ta[2]; racc[ms][n4][3] += ta[3];
                    float c1[4], c2[4];
                    mma16816_zc(c1, af[1][ms], bfr[0][n4][0], bfr[0][n4][1]);   // (1,0)
                    mma16816_zc(c2, af[0][ms], bfr[1][n4][0], bfr[1][n4][1]);   // (0,1)
                    mma16816(c1, af[2][ms], bfr[0][n4][0], bfr[0][n4][1]);      // (2,0)
                    mma16816(c2, af[1][ms], bfr[1][n4][0], bfr[1][n4][1]);      // (1,1)
                    mma16816(c2, af[0][ms], bfr[2][n4][0], bfr[2][n4][1]);      // (0,2)
                    racc[ms][n4][0] += c1[0]; racc[ms][n4][1] += c1[1];
                    racc[ms][n4][2] += c1[2]; racc[ms][n4][3] += c1[3];
                    racc[ms][n4][0] += c2[0]; racc[ms][n4][1] += c2[1];
                    racc[ms][n4][2] += c2[2]; racc[ms][n4][3] += c2[3];
                }
            }
        }
        __syncthreads();
    }

    // ---- epilogue: T' splits + deterministic diag partials ----
#pragma unroll
    for (int ms = 0; ms < 2; ms++) {
#pragma unroll
        for (int half = 0; half < 2; half++) {
            int gi = rowBase + wr * 32 + ms * 16 + g + half * 8;
            size_t rowo = ((size_t)(b * NN + gi)) * NN;
            float part = 0.f;
#pragma unroll
            for (int n4 = 0; n4 < 4; n4++) {
                int l0 = colBase + wc * 32 + n4 * 8 + tig * 2;
                float c0 = racc[ms][n4][half * 2 + 0];
                float c1 = racc[ms][n4][half * 2 + 1];
                float2 wv = *reinterpret_cast<const float2*>(&Wfull[(size_t)gi * NN + l0]);
                part += c0 * wv.x + c1 * wv.y;
                __nv_bfloat16 x1, x2, x3, y1, y2, y3;
                split3(c0, x1, x2, x3);
                split3(c1, y1, y2, y3);
                union { __nv_bfloat16 h[2]; uint32_t u; } u1, u2, u3;
                u1.h[0] = x1; u1.h[1] = y1;
                u2.h[0] = x2; u2.h[1] = y2;
                u3.h[0] = x3; u3.h[1] = y3;
                *reinterpret_cast<uint32_t*>(&g_Ts[0][rowo + l0]) = u1.u;
                *reinterpret_cast<uint32_t*>(&g_Ts[1][rowo + l0]) = u2.u;
                *reinterpret_cast<uint32_t*>(&g_Ts[2][rowo + l0]) = u3.u;
            }
            part += __shfl_xor_sync(0xffffffffu, part, 1);
            part += __shfl_xor_sync(0xffffffffu, part, 2);
            if (tig == 0)
                g_diagP[coltile * 2 + wc][b * NN + gi] = part;
        }
    }
}

// ============ GEMM2: 256 thr, 8 warps (4x2), CTA tile 64x64, 3 CTAs/SM ====================
// C = T' @ W^T symmetric -> rho epilogue + Cov_next splits; upper-tri 64x64 tiles (grid 36x1xBB)
#define TILE64 (64 * ROW2)               // 5120 B
#define STAGEG2 (6 * TILE64)             // 30720 B
#define SMEM_G2 (2 * STAGEG2)            // 61440 B per CTA -> 3 CTAs/SM

__global__ void __launch_bounds__(256, 3)
mma_gemm2_kernel(float* __restrict__ fdst, const float* __restrict__ s_nxt) {
    extern __shared__ char sm[];
    const uint32_t sb = smem_u32(sm);
    const int tid = threadIdx.x;
    const int wid = tid >> 5;
    const int lane = tid & 31;
    const int g = lane >> 2;
    const int tig = lane & 3;
    const int wr = wid & 3;             // warp row (16 rows of 64)
    const int wc = wid >> 2;            // warp col (32 cols of 64)
    const int b = blockIdx.z;

    int m = blockIdx.x;
    int t = 0, base = 0;
    while (base + t + 1 <= m) { t++; base += t; }
    int txm = t, tym = m - base;         // txm >= tym
    const int rowBase = tym * 64;
    const int colBase = txm * 64;
    const bool offdiag = (txm != tym);

    const __nv_bfloat16* src[6] = {g_Ts[0], g_Ts[1], g_Ts[2], g_Ws[0], g_Ws[1], g_Ws[2]};
    const size_t abase = ((size_t)(b * NN + rowBase)) * NN;
    const size_t bbase = (size_t)colBase * NN;              // W^T: rows of W

    auto issue_chunk = [&](int c, int st) {
        uint32_t dstBase = sb + st * STAGEG2;
#pragma unroll
        for (int i = 0; i < 6; i++) {
            int idx = tid + i * 256;                         // 0..1535
            int tile = idx >> 8;                             // 0..5
            int rem = idx & 255;
            int r = rem >> 2, c4 = rem & 3;
            size_t go = (tile < 3 ? abase : bbase) + (size_t)r * NN + c * KC2 + c4 * 8;
            CP_ASYNC16(dstBase + tile * TILE64 + r * ROW2 + c4 * 16,
                       (const void*)(src[tile] + go));
        }
    };

    const uint32_t aBase = sb + (uint32_t)(wr * 16 + (lane & 15)) * ROW2 + ((lane >> 4) * 16);
    const uint32_t bBase = sb + 3 * TILE64
                              + (uint32_t)(wc * 32 + ((lane >> 4) << 3) + (lane & 7)) * ROW2
                              + (((lane >> 3) & 1) * 16);

    float racc[4][4];
#pragma unroll
    for (int j = 0; j < 4; j++)
#pragma unroll
        for (int q = 0; q < 4; q++) racc[j][q] = 0.f;

    issue_chunk(0, 0);
    CP_COMMIT();

    for (int c = 0; c < 16; c++) {
        int st = c & 1;
        if (c + 1 < 16) {
            issue_chunk(c + 1, (c + 1) & 1);
            CP_COMMIT();
            CP_WAIT1();
        } else {
            CP_WAIT0();
        }
        __syncthreads();

        uint32_t stOff = (uint32_t)st * STAGEG2;
#pragma unroll
        for (int ks = 0; ks < 2; ks++) {
            uint32_t kOff = stOff + ks * 32;
            uint32_t af[3][4];
#pragma unroll
            for (int p = 0; p < 3; p++)
                LDSM_X4(af[p][0], af[p][1], af[p][2], af[p][3],
                        aBase + kOff + p * TILE64);
            uint32_t bfr[3][4][2];
#pragma unroll
            for (int q = 0; q < 3; q++) {
#pragma unroll
                for (int j = 0; j < 2; j++)
                    LDSM_X4(bfr[q][2 * j][0], bfr[q][2 * j][1], bfr[q][2 * j + 1][0], bfr[q][2 * j + 1][1],
                            bBase + kOff + q * TILE64 + j * (16 * ROW2));
            }
#pragma unroll
            for (int n4 = 0; n4 < 4; n4++) {
                float ta[4];
                mma16816_zc(ta, af[0], bfr[0][n4][0], bfr[0][n4][1]);   // (0,0) lead
                racc[n4][0] += ta[0]; racc[n4][1] += ta[1];
                racc[n4][2] += ta[2]; racc[n4][3] += ta[3];
                float c1[4], c2[4];
                mma16816_zc(c1, af[1], bfr[0][n4][0], bfr[0][n4][1]);   // (1,0)
                mma16816_zc(c2, af[0], bfr[1][n4][0], bfr[1][n4][1]);   // (0,1)
                mma16816(c1, af[2], bfr[0][n4][0], bfr[0][n4][1]);      // (2,0)
                mma16816(c2, af[1], bfr[1][n4][0], bfr[1][n4][1]);      // (1,1)
                mma16816(c2, af[0], bfr[2][n4][0], bfr[2][n4][1]);      // (0,2)
                racc[n4][0] += c1[0]; racc[n4][1] += c1[1];
                racc[n4][2] += c1[2]; racc[n4][3] += c1[3];
                racc[n4][0] += c2[0]; racc[n4][1] += c2[1];
                racc[n4][2] += c2[2]; racc[n4][3] += c2[3];
            }
        }
        __syncthreads();
    }

    // ---- epilogue: rho + Cov_next splits (warp tile 16x32) ----
    float* tb = (float*)sm;                 // 64 x 68 f32 transpose buffer (17.4 KB)
#pragma unroll
    for (int half = 0; half < 2; half++) {
        int gl = wr * 16 + g + half * 8;     // local row 0..63
        int gi = rowBase + gl;
        size_t rowo = ((size_t)(b * NN + gi)) * NN;
        float chI = __ldg(&g_chi[b * NN + gi]);
        float soI = __ldg(&g_sout[b * NN + gi]);
        float snI = __ldg(&s_nxt[b * NN + gi]);
#pragma unroll
        for (int n4 = 0; n4 < 4; n4++) {
            int lc = wc * 32 + n4 * 8 + tig * 2;   // local col 0..63
            int l0 = colBase + lc;
            float rv[2], cvv[2];
#pragma unroll
            for (int q = 0; q < 2; q++) {
                int l = l0 + q;
                float cv = racc[n4][half * 2 + q];
                float chL = __ldg(&g_chi[b * NN + l]);
                float soL = __ldg(&g_sout[b * NN + l]);
                float snL = __ldg(&s_nxt[b * NN + l]);
                float denom = soI * soL;
                float qq = (denom > 1e-12f) ? cv / denom : 0.0f;
                rv[q] = (gi == l) ? 1.0f : chI * chL * qq;
                cvv[q] = rv[q] * snI * snL;
                if (offdiag) tb[(lc + q) * 68 + gl] = rv[q];
            }
            __nv_bfloat16 x1, x2, x3, y1, y2, y3;
            split3(cvv[0], x1, x2, x3);
            split3(cvv[1], y1, y2, y3);
            union { __nv_bfloat16 h[2]; uint32_t u; } u1, u2, u3;
            u1.h[0] = x1; u1.h[1] = y1;
            u2.h[0] = x2; u2.h[1] = y2;
            u3.h[0] = x3; u3.h[1] = y3;
            *reinterpret_cast<uint32_t*>(&g_Cs[0][rowo + l0]) = u1.u;
            *reinterpret_cast<uint32_t*>(&g_Cs[1][rowo + l0]) = u2.u;
            *reinterpret_cast<uint32_t*>(&g_Cs[2][rowo + l0]) = u3.u;
            if (fdst)
                *reinterpret_cast<float2*>(&fdst[rowo + l0]) = make_float2(rv[0], rv[1]);
        }
    }
    if (offdiag) {
        __syncthreads();
        // mirror: global rows colBase..+64, cols rowBase..+64
        int r2 = tid >> 2;                  // 0..63
        int c0 = (tid & 3) * 16;
        int giM = colBase + r2;
        size_t mrow = ((size_t)(b * NN + giM)) * NN + rowBase + c0;
        const float* trow = tb + r2 * 68 + c0;
        float* frow = fdst ? (fdst + mrow) : (float*)0;
        float snI = __ldg(&s_nxt[b * NN + giM]);
#pragma unroll
        for (int j = 0; j < 16; j += 4) {
            float r0 = trow[j + 0], r1 = trow[j + 1], r2v = trow[j + 2], r3 = trow[j + 3];
            float4 snL = *reinterpret_cast<const float4*>(&s_nxt[b * NN + rowBase + c0 + j]);
            float v0 = r0 * snI * snL.x, v1 = r1 * snI * snL.y;
            float v2 = r2v * snI * snL.z, v3 = r3 * snI * snL.w;
            union { __nv_bfloat16 h[4]; uint2 u; } p1, p2, p3;
            split3(v0, p1.h[0], p2.h[0], p3.h[0]);
            split3(v1, p1.h[1], p2.h[1], p3.h[1]);
            split3(v2, p1.h[2], p2.h[2], p3.h[2]);
            split3(v3, p1.h[3], p2.h[3], p3.h[3]);
            *reinterpret_cast<uint2*>(&g_Cs[0][mrow + j]) = p1.u;
            *reinterpret_cast<uint2*>(&g_Cs[1][mrow + j]) = p2.u;
            *reinterpret_cast<uint2*>(&g_Cs[2][mrow + j]) = p3.u;
            if (frow)
                *reinterpret_cast<float4*>(frow + j) = make_float4(r0, r1, r2v, r3);
        }
    }
}

// ---------------- launch ----------------
extern "C" void kernel_launch(void* const* d_in, const int* in_sizes, int n_in,
                              void* d_out, int out_size) {
    const float* u_in     = (const float*)d_in[0];
    const float* s_in     = (const float*)d_in[1];
    const float* rho_in   = (const float*)d_in[2];
    const float* uext     = (const float*)d_in[3];
    const float* sext     = (const float*)d_in[4];
    const float* W        = (const float*)d_in[5];
    const float* bias     = (const float*)d_in[6];
    const float* Wext     = (const float*)d_in[7];
    const float* bext     = (const float*)d_in[8];
    const float* wmean    = (const float*)d_in[9];
    const float* bmean    = (const float*)d_in[10];
    const float* wmeanext = (const float*)d_in[11];
    const float* bmeanext = (const float*)d_in[12];
    (void)in_sizes; (void)n_in; (void)out_size;

    float* out = (float*)d_out;
    float* out_u = out;
    float* out_s = out + BB * NN;
    float* out_rho = out + 2 * BB * NN;

    cudaFuncSetAttribute(mma_gemm1_kernel, cudaFuncAttributeMaxDynamicSharedMemorySize, SMEM_G1);
    cudaFuncSetAttribute(mma_gemm2_kernel, cudaFuncAttributeMaxDynamicSharedMemorySize, SMEM_G2);

    float *uA, *sA, *uB, *sB;
    cudaGetSymbolAddress((void**)&uA, g_uA);
    cudaGetSymbolAddress((void**)&sA, g_sA);
    cudaGetSymbolAddress((void**)&uB, g_uB);
    cudaGetSymbolAddress((void**)&sB, g_sB);

    dim3 g0(8, 4, BB);       // GEMM1: 128x64 tiles, full grid
    dim3 g1(36, 1, BB);      // GEMM2: upper-triangle 64x64 tiles
    float* u_cur = uA; float* s_cur = sA;
    float* u_nxt = uB; float* s_nxt = sB;

    // t = 0 (ordered so GEMM1 is launch index 3 -> ncu profiles it)
    init_copy_kernel<<<32, 512>>>(u_in, s_in);                               // 0
    wsplit_kernel<<<NN * NN / 4 / 256, 256>>>(W);                            // 1
    csplit0_kernel<<<SZT / 4 / 256, 256>>>(rho_in, s_in);                    // 2
    mma_gemm1_kernel<<<g0, 256, SMEM_G1>>>(W);                               // 3  <-- profiled
    build_tables_kernel<<<1, 1024>>>();                                      // 4
    ext_gemm_kernel<<<dim3(64, 32), 256>>>(Wext, uext, sext, bext);          // 5
    ext_bn_kernel<<<4, 128>>>(wmeanext, bmeanext);                           // 6
    ulin_kernel<<<dim3(64, 32), 256>>>(W, bias, u_cur);                      // 7
    bn_act_kernel<<<64, 256>>>(wmean, bmean, u_nxt, s_nxt,
                               (float*)nullptr, (float*)nullptr);            // 8
    mma_gemm2_kernel<<<g1, 256, SMEM_G2>>>((float*)nullptr, s_nxt);          // 9
    { float* t = u_cur; u_cur = u_nxt; u_nxt = t; }
    { float* t = s_cur; s_cur = s_nxt; s_nxt = t; }

    for (int t = 1; t < SEQ; t++) {
        bool last = (t == SEQ - 1);
        mma_gemm1_kernel<<<g0, 256, SMEM_G1>>>(W);
        ulin_kernel<<<dim3(64, 32), 256>>>(W, bias, u_cur);
        bn_act_kernel<<<64, 256>>>(wmean, bmean, u_nxt, s_nxt,
                                   last ? out_u : (float*)nullptr,
                                   last ? out_s : (float*)nullptr);
        mma_gemm2_kernel<<<g1, 256, SMEM_G2>>>(last ? out_rho : (float*)nullptr, s_nxt);
        float* tu = u_cur; u_cur = u_nxt; u_nxt = tu;
        float* ts = s_cur; s_cur = s_nxt; s_nxt = ts;
    }
}